// round 1
// baseline (speedup 1.0000x reference)
#include <cuda_runtime.h>
#include <math.h>

#define BB 4
#define NN 64
#define NS 16      // X slices kept
#define MK 16      // y,z modes
#define NC 32      // channels
#define SCALE (1.0f/131072.0f)   // 1/(64*64*32)
#define PI_D 3.14159265358979323846

// Scratch (float2 = complex)
__device__ float2 g_A1[BB*NS*NN*MK*NC];   // [b][Xs][y][kz][c]   16.8 MB
__device__ float2 g_A2[BB*NS*MK*MK*NC];   // [b][m][c]            4.2 MB
__device__ float2 g_A3[BB*NS*MK*MK*NC];   // [b][m][i]            4.2 MB
__device__ float2 g_A4[BB*NC*NS*MK*MK];   // [b][o][m]            4.2 MB
__device__ float2 g_A5[BB*NS*MK*MK*NC];   // [b][m][c]            4.2 MB
__device__ float2 g_A6[BB*NS*NN*MK*NC];   // [b][Xs][y][kz][c]   16.8 MB

// ---------------- K1: forward DFT over z (64 -> 16 modes), real input ----------
__global__ __launch_bounds__(512) void k1_dftz(const float* __restrict__ x) {
    __shared__ float sx[64*32];
    __shared__ float2 tw[64];
    int bid = blockIdx.x;              // b*1024 + Xs*64 + y
    int y  = bid & 63;
    int Xs = (bid >> 6) & 15;
    int b  = bid >> 10;
    int tid = threadIdx.x;
    if (tid < 64) {
        double ang = -2.0 * PI_D * (double)tid / 64.0;
        tw[tid] = make_float2((float)cos(ang), (float)sin(ang));
    }
    const float* src = x + ((((size_t)b*64 + Xs)*64 + y)*64)*32;
    #pragma unroll
    for (int r = 0; r < 4; r++) sx[tid + r*512] = src[tid + r*512];
    __syncthreads();
    int c = tid & 31, kz = tid >> 5;
    float2 acc = make_float2(0.f, 0.f);
    #pragma unroll 8
    for (int z = 0; z < 64; z++) {
        float v = sx[z*32 + c];
        float2 w = tw[(kz*z) & 63];
        acc.x += v * w.x;
        acc.y += v * w.y;
    }
    g_A1[((((b*16 + Xs)*64 + y)*16 + kz)*32) + c] = acc;
}

// ---------------- K2: forward DFT over y (64 -> 16 modes), complex -------------
__global__ __launch_bounds__(512) void k2_dfty() {
    __shared__ float2 si[64*32];
    __shared__ float2 tw[64];
    int bid = blockIdx.x;              // b*256 + Xs*16 + kz
    int kz = bid & 15;
    int Xs = (bid >> 4) & 15;
    int b  = bid >> 8;
    int tid = threadIdx.x;
    if (tid < 64) {
        double ang = -2.0 * PI_D * (double)tid / 64.0;
        tw[tid] = make_float2((float)cos(ang), (float)sin(ang));
    }
    #pragma unroll
    for (int r = 0; r < 4; r++) {
        int idx = tid + r*512;
        int yy = idx >> 5, cc = idx & 31;
        si[idx] = g_A1[(((b*16 + Xs)*64 + yy)*16 + kz)*32 + cc];
    }
    __syncthreads();
    int c = tid & 31, ky = tid >> 5;
    float2 acc = make_float2(0.f, 0.f);
    #pragma unroll 8
    for (int yy = 0; yy < 64; yy++) {
        float2 a = si[yy*32 + c];
        float2 w = tw[(ky*yy) & 63];
        acc.x += a.x*w.x - a.y*w.y;
        acc.y += a.x*w.y + a.y*w.x;
    }
    g_A2[(((b*16 + Xs)*16 + ky)*16 + kz)*32 + c] = acc;
}

// ---------------- K3: forward DFT over channel axis (32 -> 32) -----------------
__global__ __launch_bounds__(512) void k3_dftc() {
    __shared__ float2 si[16*32];
    __shared__ float2 tw[32];
    int site0 = blockIdx.x * 16;       // global site = b*4096 + m
    int tid = threadIdx.x;
    if (tid < 32) {
        double ang = -2.0 * PI_D * (double)tid / 32.0;
        tw[tid] = make_float2((float)cos(ang), (float)sin(ang));
    }
    si[tid] = g_A2[site0*32 + tid];    // 512 contiguous complex
    __syncthreads();
    int i = tid & 31, s = tid >> 5;
    float2 acc = make_float2(0.f, 0.f);
    #pragma unroll
    for (int c = 0; c < 32; c++) {
        float2 a = si[s*32 + c];
        float2 w = tw[(i*c) & 31];
        acc.x += a.x*w.x - a.y*w.y;
        acc.y += a.x*w.y + a.y*w.x;
    }
    g_A3[(site0 + s)*32 + i] = acc;
}

// ---------------- K4: per-mode 32x32 complex channel mix -----------------------
// out[b][o][m] = sum_i A3[b][m][i] * (wr + j*wi)[i][o][m] ; scaled by 1/131072
__global__ __launch_bounds__(128) void k4_mix(const float* __restrict__ wr_g,
                                              const float* __restrict__ wi_g) {
    __shared__ float2 in_s[4*32*33];   // [b][i][m_local], padded stride 33
    int m0 = blockIdx.x * 32;
    int o0 = blockIdx.y * 8;
    int tid = threadIdx.x;             // 128
    #pragma unroll
    for (int r = 0; r < 32; r++) {
        int idx = tid + r*128;         // (b_, m_, i) with i fastest
        int i  = idx & 31;
        int m_ = (idx >> 5) & 31;
        int b_ = idx >> 10;
        in_s[(b_*32 + i)*33 + m_] = g_A3[((b_*4096) + m0 + m_)*32 + i];
    }
    __syncthreads();
    int m_l = tid & 31;
    int b_  = tid >> 5;
    for (int o = o0; o < o0 + 8; o++) {
        float2 acc = make_float2(0.f, 0.f);
        #pragma unroll
        for (int i = 0; i < 32; i++) {
            float2 a = in_s[(b_*32 + i)*33 + m_l];
            float wr = wr_g[(i*32 + o)*4096 + m0 + m_l];
            float wi = wi_g[(i*32 + o)*4096 + m0 + m_l];
            acc.x += a.x*wr - a.y*wi;
            acc.y += a.x*wi + a.y*wr;
        }
        acc.x *= SCALE; acc.y *= SCALE;
        g_A4[(b_*32 + o)*4096 + m0 + m_l] = acc;
    }
}

// ---------------- K5: inverse DFT over channel axis (32 -> 32) -----------------
__global__ __launch_bounds__(512) void k5_idftc() {
    __shared__ float2 si[32*16];       // [o][m_local]
    __shared__ float2 tw[32];
    int b  = blockIdx.x >> 8;
    int m0 = (blockIdx.x & 255) * 16;
    int tid = threadIdx.x;             // 512
    if (tid < 32) {
        double ang = 2.0 * PI_D * (double)tid / 32.0;
        tw[tid] = make_float2((float)cos(ang), (float)sin(ang));
    }
    {
        int o = tid >> 4, ml = tid & 15;
        si[o*16 + ml] = g_A4[(b*32 + o)*4096 + m0 + ml];
    }
    __syncthreads();
    int c = tid & 31, ml = tid >> 5;
    float2 acc = make_float2(0.f, 0.f);
    #pragma unroll
    for (int o = 0; o < 32; o++) {
        float2 a = si[o*16 + ml];
        float2 w = tw[(o*c) & 31];
        acc.x += a.x*w.x - a.y*w.y;
        acc.y += a.x*w.y + a.y*w.x;
    }
    g_A5[(b*4096 + m0 + ml)*32 + c] = acc;
}

// ---------------- K6: inverse DFT over y (16 modes -> 64) ----------------------
__global__ __launch_bounds__(512) void k6_idfty() {
    __shared__ float2 si[16*32];
    __shared__ float2 tw[64];
    int bid = blockIdx.x;              // b*256 + Xs*16 + kz
    int kz = bid & 15;
    int Xs = (bid >> 4) & 15;
    int b  = bid >> 8;
    int tid = threadIdx.x;
    if (tid < 64) {
        double ang = 2.0 * PI_D * (double)tid / 64.0;
        tw[tid] = make_float2((float)cos(ang), (float)sin(ang));
    }
    {
        int ky = tid >> 5, cc = tid & 31;
        si[tid] = g_A5[((b*4096) + Xs*256 + ky*16 + kz)*32 + cc];
    }
    __syncthreads();
    #pragma unroll
    for (int r = 0; r < 4; r++) {
        int idx = threadIdx.x + r*512;
        int yy = idx >> 5, c = idx & 31;
        float2 acc = make_float2(0.f, 0.f);
        #pragma unroll
        for (int ky = 0; ky < 16; ky++) {
            float2 a = si[ky*32 + c];
            float2 w = tw[(ky*yy) & 63];
            acc.x += a.x*w.x - a.y*w.y;
            acc.y += a.x*w.y + a.y*w.x;
        }
        g_A6[(((b*16 + Xs)*64 + yy)*16 + kz)*32 + c] = acc;
    }
}

// ---------------- K7: inverse DFT over z (16 -> 64), real part -----------------
__global__ __launch_bounds__(512) void k7_idftz(float* __restrict__ out) {
    __shared__ float2 si[16*32];
    __shared__ float2 tw[64];
    int bid = blockIdx.x;              // b*1024 + Xs*64 + y
    int y  = bid & 63;
    int Xs = (bid >> 6) & 15;
    int b  = bid >> 10;
    int tid = threadIdx.x;
    if (tid < 64) {
        double ang = 2.0 * PI_D * (double)tid / 64.0;
        tw[tid] = make_float2((float)cos(ang), (float)sin(ang));
    }
    si[tid] = g_A6[((((b*16 + Xs)*64 + y)*16)*32) + tid];  // 512 contiguous
    __syncthreads();
    float* dst = out + ((((size_t)b*64 + Xs)*64 + y)*64)*32;
    #pragma unroll
    for (int r = 0; r < 4; r++) {
        int idx = threadIdx.x + r*512;
        int z = idx >> 5, c = idx & 31;
        float acc = 0.f;
        #pragma unroll
        for (int kz = 0; kz < 16; kz++) {
            float2 a = si[kz*32 + c];
            float2 w = tw[(kz*z) & 63];
            acc += a.x*w.x - a.y*w.y;
        }
        dst[idx] = acc;
    }
}

extern "C" void kernel_launch(void* const* d_in, const int* in_sizes, int n_in,
                              void* d_out, int out_size) {
    const float* x  = (const float*)d_in[0];
    const float* wr = (const float*)d_in[1];
    const float* wi = (const float*)d_in[2];
    float* out = (float*)d_out;

    // Zero the X >= 16 slices (ifft over (Y,Z,O) leaves X untouched; out_ft is
    // zero-padded there, so output is exactly 0 for X in [16,64)).
    for (int b = 0; b < BB; b++) {
        size_t off = (((size_t)b*64 + 16)*64*64)*32;
        cudaMemsetAsync(out + off, 0, (size_t)48*64*64*32*sizeof(float), 0);
    }

    k1_dftz<<<BB*NS*NN, 512>>>(x);          // 4096 blocks
    k2_dfty<<<BB*NS*MK, 512>>>();           // 1024 blocks
    k3_dftc<<<BB*NS*MK*MK/16, 512>>>();     // 1024 blocks
    dim3 g4(128, 4);
    k4_mix<<<g4, 128>>>(wr, wi);            // 512 blocks
    k5_idftc<<<BB*256, 512>>>();            // 1024 blocks
    k6_idfty<<<BB*NS*MK, 512>>>();          // 1024 blocks
    k7_idftz<<<BB*NS*NN, 512>>>(out);       // 4096 blocks
}

// round 2
// speedup vs baseline: 1.3282x; 1.3282x over previous
#include <cuda_runtime.h>
#include <math.h>

#define PI_D 3.14159265358979323846
#define SCALE (1.0f/131072.0f)   // 1/(64*64*32)

// Intermediates: m = Xs*256 + ky*16 + kz  (matches weight mode layout)
__device__ float2 g_A2[4*4096*32];   // [b][m][c]  after forward z,y DFT
__device__ float2 g_A5[4*4096*32];   // [b][m][c]  after c-DFT + mix + inv o-DFT

// ============================================================================
// Kernel A: forward DFT over z (64->16) and y (64->16), per (b, Xs, cg of 8 ch)
// ============================================================================
__global__ __launch_bounds__(512) void kA(const float* __restrict__ x) {
    __shared__ float2 t1[64*136];     // [y][kz*8+c], row pad 128->136
    __shared__ float2 tw[64];         // (cos, sin) positive angle
    int bid = blockIdx.x;             // b*64 + Xs*4 + cg
    int cg = bid & 3;
    int Xs = (bid >> 2) & 15;
    int b  = bid >> 6;
    int t = threadIdx.x;
    if (t < 64) {
        double ang = 2.0*PI_D*(double)t/64.0;
        tw[t] = make_float2((float)cos(ang), (float)sin(ang));
    }
    __syncthreads();

    // ---- stage 1: z-DFT. thread = (y, c); 16 kz accumulators in registers.
    {
        int c = t & 7, y = t >> 3;
        const float* src = x + ((((size_t)b*64 + Xs)*64 + y)*64)*32 + cg*8 + c;
        float ar[16], ai[16];
        #pragma unroll
        for (int k = 0; k < 16; k++) { ar[k] = 0.f; ai[k] = 0.f; }
        #pragma unroll 4
        for (int z = 0; z < 64; z++) {
            float v = src[(size_t)z*32];
            #pragma unroll
            for (int k = 0; k < 16; k++) {
                float2 w = tw[(k*z) & 63];       // e^{-i} => (c, -s)
                ar[k] += v * w.x;
                ai[k] -= v * w.y;
            }
        }
        #pragma unroll
        for (int k = 0; k < 16; k++)
            t1[y*136 + k*8 + c] = make_float2(ar[k], ai[k]);
    }
    __syncthreads();

    // ---- stage 2: y-DFT. thread = (c, kz, ky-quarter); each does 4 ky.
    {
        int c = t & 7, kz = (t >> 3) & 15, kyq = t >> 7;
        float2* dst = g_A2 + ((size_t)(b*4096 + Xs*256 + kz))*32 + cg*8 + c;
        #pragma unroll
        for (int j = 0; j < 4; j++) {
            int ky = kyq*4 + j;
            float or_ = 0.f, oi = 0.f;
            #pragma unroll 4
            for (int y = 0; y < 64; y++) {
                float2 a = t1[y*136 + kz*8 + c];
                float2 w = tw[(ky*y) & 63];      // e^{-i}: re=ac+as', ...
                or_ += a.x*w.x + a.y*w.y;        // (ax+iay)(c - is)
                oi  += a.y*w.x - a.x*w.y;
            }
            dst[(size_t)ky*512] = make_float2(or_, oi);  // ky*16*32
        }
    }
}

// ============================================================================
// Kernel B: per 16-mode chunk (all 4 batches): c-DFT -> 32x32 mix -> inv o-DFT
// ============================================================================
__global__ __launch_bounds__(512) void kB(const float* __restrict__ wr_g,
                                          const float* __restrict__ wi_g) {
    __shared__ float2 sA[4*16*32];    // [b][m][c]  input, contiguous
    __shared__ float2 sF[64*33];      // [(b*16+m)][i], pad 33
    __shared__ float2 sG[64*33];      // [(b*16+m)][o], pad 33
    __shared__ float2 tw[32];
    int m0 = blockIdx.x * 16;
    int t = threadIdx.x;
    if (t < 32) {
        double ang = 2.0*PI_D*(double)t/32.0;
        tw[t] = make_float2((float)cos(ang), (float)sin(ang));
    }
    // load A2: 2048 float2, 4 per thread (one b each)
    #pragma unroll
    for (int r = 0; r < 4; r++)
        sA[r*512 + t] = g_A2[((size_t)(r*4096 + m0))*32 + t];
    __syncthreads();

    // ---- stage 1: forward DFT over c. thread = (i, m); loop b.
    {
        int i = t & 31, ml = t >> 5;
        #pragma unroll
        for (int b = 0; b < 4; b++) {
            float re = 0.f, im = 0.f;
            #pragma unroll 4
            for (int c = 0; c < 32; c++) {
                float2 a = sA[(b*16 + ml)*32 + c];
                float2 w = tw[(i*c) & 31];       // e^{-i}
                re += a.x*w.x + a.y*w.y;
                im += a.y*w.x - a.x*w.y;
            }
            sF[(b*16 + ml)*33 + i] = make_float2(re, im);
        }
    }
    __syncthreads();

    // ---- stage 2: channel mix. thread = (m, o); weights loaded once, 4 b reuse.
    {
        int ml = t & 15, o = t >> 4;
        float r0=0,i0=0,r1=0,i1=0,r2=0,i2=0,r3=0,i3=0;
        const float* wrp = wr_g + (size_t)o*4096 + m0 + ml;
        const float* wip = wi_g + (size_t)o*4096 + m0 + ml;
        #pragma unroll 2
        for (int i = 0; i < 32; i++) {
            float wr = wrp[(size_t)i*131072];    // (i*32)*4096
            float wi = wip[(size_t)i*131072];
            float2 f0 = sF[( 0 + ml)*33 + i];
            float2 f1 = sF[(16 + ml)*33 + i];
            float2 f2 = sF[(32 + ml)*33 + i];
            float2 f3 = sF[(48 + ml)*33 + i];
            r0 += f0.x*wr - f0.y*wi;  i0 += f0.x*wi + f0.y*wr;
            r1 += f1.x*wr - f1.y*wi;  i1 += f1.x*wi + f1.y*wr;
            r2 += f2.x*wr - f2.y*wi;  i2 += f2.x*wi + f2.y*wr;
            r3 += f3.x*wr - f3.y*wi;  i3 += f3.x*wi + f3.y*wr;
        }
        sG[( 0 + ml)*33 + o] = make_float2(r0, i0);
        sG[(16 + ml)*33 + o] = make_float2(r1, i1);
        sG[(32 + ml)*33 + o] = make_float2(r2, i2);
        sG[(48 + ml)*33 + o] = make_float2(r3, i3);
    }
    __syncthreads();

    // ---- stage 3: inverse DFT over o -> c, with 1/131072 scale. thread=(c,m).
    {
        int c = t & 31, ml = t >> 5;
        #pragma unroll
        for (int b = 0; b < 4; b++) {
            float re = 0.f, im = 0.f;
            #pragma unroll 4
            for (int o = 0; o < 32; o++) {
                float2 g = sG[(b*16 + ml)*33 + o];
                float2 w = tw[(o*c) & 31];       // e^{+i}
                re += g.x*w.x - g.y*w.y;
                im += g.x*w.y + g.y*w.x;
            }
            g_A5[((size_t)(b*4096 + m0 + ml))*32 + c] =
                make_float2(re*SCALE, im*SCALE);
        }
    }
}

// ============================================================================
// Kernel C: inverse DFT over ky (16->64) and kz (16->64, real), per (b,Xs,cg8)
// ============================================================================
__global__ __launch_bounds__(512) void kC(float* __restrict__ out) {
    __shared__ float2 sIn[16*16*8];   // [ky][kz][c]
    __shared__ float2 t1[64*128];     // [y][kz*8+c]
    __shared__ float2 tw[64];
    int bid = blockIdx.x;             // b*64 + Xs*4 + cg
    int cg = bid & 3;
    int Xs = (bid >> 2) & 15;
    int b  = bid >> 6;
    int t = threadIdx.x;
    if (t < 64) {
        double ang = 2.0*PI_D*(double)t/64.0;
        tw[t] = make_float2((float)cos(ang), (float)sin(ang));
    }
    // load A5 slice: 2048 float2, 4 per thread
    #pragma unroll
    for (int r = 0; r < 4; r++) {
        int idx = t + r*512;
        int c = idx & 7, kz = (idx >> 3) & 15, ky = idx >> 7;
        sIn[idx] = g_A5[((size_t)(b*4096 + Xs*256 + ky*16 + kz))*32 + cg*8 + c];
    }
    __syncthreads();

    // ---- stage 1: inverse ky-DFT. thread = (c, kz, y-group of 16); regs acc.
    {
        int c = t & 7, kz = (t >> 3) & 15, yg = t >> 7;
        float ar[16], ai[16];
        #pragma unroll
        for (int j = 0; j < 16; j++) { ar[j] = 0.f; ai[j] = 0.f; }
        #pragma unroll 2
        for (int ky = 0; ky < 16; ky++) {
            float2 a = sIn[(ky*16 + kz)*8 + c];
            #pragma unroll
            for (int j = 0; j < 16; j++) {
                int y = yg*16 + j;
                float2 w = tw[(ky*y) & 63];      // e^{+i}
                ar[j] += a.x*w.x - a.y*w.y;
                ai[j] += a.x*w.y + a.y*w.x;
            }
        }
        #pragma unroll
        for (int j = 0; j < 16; j++)
            t1[(yg*16 + j)*128 + kz*8 + c] = make_float2(ar[j], ai[j]);
    }
    __syncthreads();

    // ---- stage 2: inverse kz-DFT, real part only. thread = (c, z); loop y.
    {
        int c = t & 7, z = t >> 3;
        float* dst = out + ((((size_t)b*64 + Xs)*64)*64 + z)*32 + cg*8 + c;
        for (int y = 0; y < 64; y++) {
            float acc = 0.f;
            #pragma unroll
            for (int kz = 0; kz < 16; kz++) {
                float2 a = t1[y*128 + kz*8 + c];
                float2 w = tw[(kz*z) & 63];      // e^{+i}, take real
                acc += a.x*w.x - a.y*w.y;
            }
            dst[(size_t)y*2048] = acc;           // y*64*32
        }
    }
}

extern "C" void kernel_launch(void* const* d_in, const int* in_sizes, int n_in,
                              void* d_out, int out_size) {
    const float* x  = (const float*)d_in[0];
    const float* wr = (const float*)d_in[1];
    const float* wi = (const float*)d_in[2];
    float* out = (float*)d_out;

    // Output is exactly zero for X >= 16 (no X-axis transform; out_ft zero-padded)
    for (int b = 0; b < 4; b++) {
        size_t off = (((size_t)b*64 + 16)*64*64)*32;
        cudaMemsetAsync(out + off, 0, (size_t)48*64*64*32*sizeof(float), 0);
    }

    kA<<<256, 512>>>(x);        // forward z,y DFT
    kB<<<256, 512>>>(wr, wi);   // c-DFT + mix + inverse o-DFT
    kC<<<256, 512>>>(out);      // inverse ky,kz DFT
}

// round 3
// speedup vs baseline: 2.1173x; 1.5941x over previous
#include <cuda_runtime.h>
#include <math.h>

#define PI_D 3.14159265358979323846
#define SCALE (1.0f/131072.0f)   // 1/(64*64*32)

// Intermediates: m = Xs*256 + ky*16 + kz  (matches weight mode layout)
__device__ float2 g_A2[4*4096*32];   // [b][m][c]  after forward z,y DFT
__device__ float2 g_A5[4*4096*32];   // [b][m][c]  after c-DFT + mix + inv o-DFT

// ============================================================================
// Kernel A: forward DFT over z (64->16) and y (64->16), radix-4 decimated.
// Block = (b, Xs, cg of 8 channels). tw[n] = (cos, sin)(2 pi n / 64).
// e^{-i theta} = (cw, -sw).
// ============================================================================
__global__ __launch_bounds__(512) void kA(const float* __restrict__ x) {
    __shared__ float2 t1[64*136];     // [y][kz*8+c], row pad 128->136
    __shared__ float2 tw[64];
    int bid = blockIdx.x;             // b*64 + Xs*4 + cg
    int cg = bid & 3;
    int Xs = (bid >> 2) & 15;
    int b  = bid >> 6;
    int t = threadIdx.x;
    if (t < 64) {
        double ang = 2.0*PI_D*(double)t/64.0;
        tw[t] = make_float2((float)cos(ang), (float)sin(ang));
    }
    __syncthreads();

    // ---- stage 1: z-DFT (64 -> 16), radix-4. thread = (y, c).
    {
        int c = t & 7, y = t >> 3;
        const float* src = x + ((((size_t)b*64 + Xs)*64 + y)*64)*32 + cg*8 + c;
        float r0[4],i0[4],r1[4],i1[4],r2[4],i2[4],r3[4],i3[4];
        #pragma unroll
        for (int m=0;m<4;m++){r0[m]=i0[m]=r1[m]=i1[m]=r2[m]=i2[m]=r3[m]=i3[m]=0.f;}
        #pragma unroll
        for (int z0 = 0; z0 < 16; z0++) {
            float v0 = src[(z0   )*32];
            float v1 = src[(z0+16)*32];
            float v2 = src[(z0+32)*32];
            float v3 = src[(z0+48)*32];
            float e02=v0+v2, e13=v1+v3;
            float s=e02+e13, d=e02-e13, p=v0-v2, q=v1-v3;
            #pragma unroll
            for (int m=0;m<4;m++) {
                { float2 w = tw[((4*m  )*z0)&63]; r0[m]+=s*w.x;         i0[m]-=s*w.y; }
                { float2 w = tw[((4*m+2)*z0)&63]; r2[m]+=d*w.x;         i2[m]-=d*w.y; }
                { float2 w = tw[((4*m+1)*z0)&63]; r1[m]+=p*w.x - q*w.y; i1[m]-=p*w.y + q*w.x; }
                { float2 w = tw[((4*m+3)*z0)&63]; r3[m]+=p*w.x + q*w.y; i3[m]+=q*w.x - p*w.y; }
            }
        }
        #pragma unroll
        for (int m=0;m<4;m++){
            t1[y*136 + (4*m  )*8 + c] = make_float2(r0[m], i0[m]);
            t1[y*136 + (4*m+1)*8 + c] = make_float2(r1[m], i1[m]);
            t1[y*136 + (4*m+2)*8 + c] = make_float2(r2[m], i2[m]);
            t1[y*136 + (4*m+3)*8 + c] = make_float2(r3[m], i3[m]);
        }
    }
    __syncthreads();

    // ---- stage 2: y-DFT (64 -> 16), radix-4. thread = (c, kz, residue r).
    {
        int c = t & 7, kz = (t >> 3) & 15, r = t >> 7;
        float ar[4], ai[4];
        #pragma unroll
        for (int m=0;m<4;m++){ar[m]=0.f; ai[m]=0.f;}
        #pragma unroll
        for (int y0 = 0; y0 < 16; y0++) {
            float2 a0 = t1[(y0   )*136 + kz*8 + c];
            float2 a1 = t1[(y0+16)*136 + kz*8 + c];
            float2 a2 = t1[(y0+32)*136 + kz*8 + c];
            float2 a3 = t1[(y0+48)*136 + kz*8 + c];
            float2 u;
            if (r == 0)      u = make_float2(a0.x+a1.x+a2.x+a3.x, a0.y+a1.y+a2.y+a3.y);
            else if (r == 2) u = make_float2(a0.x-a1.x+a2.x-a3.x, a0.y-a1.y+a2.y-a3.y);
            else {
                float pr=a0.x-a2.x, pi=a0.y-a2.y, qr=a1.x-a3.x, qi=a1.y-a3.y;
                if (r == 1) u = make_float2(pr+qi, pi-qr);   // p - i q
                else        u = make_float2(pr-qi, pi+qr);   // p + i q
            }
            #pragma unroll
            for (int m=0;m<4;m++) {
                int ky = 4*m + r;
                float2 w = tw[(ky*y0)&63];
                ar[m] += u.x*w.x + u.y*w.y;     // u * (cw - i sw)
                ai[m] += u.y*w.x - u.x*w.y;
            }
        }
        float2* dst = g_A2 + ((size_t)(b*4096 + Xs*256 + kz))*32 + cg*8 + c;
        #pragma unroll
        for (int m=0;m<4;m++)
            dst[(size_t)(4*m+r)*512] = make_float2(ar[m], ai[m]);
    }
}

// ============================================================================
// Kernel B: per 16-mode chunk (all 4 batches): c-DFT -> 32x32 mix -> inv o-DFT
// ============================================================================
__global__ __launch_bounds__(512) void kB(const float* __restrict__ wr_g,
                                          const float* __restrict__ wi_g) {
    __shared__ float2 sA[4*16*32];    // [b][m][c]
    __shared__ float2 sF[64*33];      // [(b*16+m)][i], pad 33
    __shared__ float2 sG[64*33];      // [(b*16+m)][o], pad 33
    __shared__ float2 tw[32];
    int m0 = blockIdx.x * 16;
    int t = threadIdx.x;
    if (t < 32) {
        double ang = 2.0*PI_D*(double)t/32.0;
        tw[t] = make_float2((float)cos(ang), (float)sin(ang));
    }
    #pragma unroll
    for (int r = 0; r < 4; r++)
        sA[r*512 + t] = g_A2[((size_t)(r*4096 + m0))*32 + t];
    __syncthreads();

    // stage 1: forward DFT over c. thread = (i, m); loop b.
    {
        int i = t & 31, ml = t >> 5;
        #pragma unroll
        for (int b = 0; b < 4; b++) {
            float re = 0.f, im = 0.f;
            #pragma unroll 4
            for (int c = 0; c < 32; c++) {
                float2 a = sA[(b*16 + ml)*32 + c];
                float2 w = tw[(i*c) & 31];       // e^{-i}
                re += a.x*w.x + a.y*w.y;
                im += a.y*w.x - a.x*w.y;
            }
            sF[(b*16 + ml)*33 + i] = make_float2(re, im);
        }
    }
    __syncthreads();

    // stage 2: channel mix. thread = (m, o); weights loaded once, 4 b reuse.
    {
        int ml = t & 15, o = t >> 4;
        float r0=0,i0=0,r1=0,i1=0,r2=0,i2=0,r3=0,i3=0;
        const float* wrp = wr_g + (size_t)o*4096 + m0 + ml;
        const float* wip = wi_g + (size_t)o*4096 + m0 + ml;
        #pragma unroll 2
        for (int i = 0; i < 32; i++) {
            float wr = wrp[(size_t)i*131072];
            float wi = wip[(size_t)i*131072];
            float2 f0 = sF[( 0 + ml)*33 + i];
            float2 f1 = sF[(16 + ml)*33 + i];
            float2 f2 = sF[(32 + ml)*33 + i];
            float2 f3 = sF[(48 + ml)*33 + i];
            r0 += f0.x*wr - f0.y*wi;  i0 += f0.x*wi + f0.y*wr;
            r1 += f1.x*wr - f1.y*wi;  i1 += f1.x*wi + f1.y*wr;
            r2 += f2.x*wr - f2.y*wi;  i2 += f2.x*wi + f2.y*wr;
            r3 += f3.x*wr - f3.y*wi;  i3 += f3.x*wi + f3.y*wr;
        }
        sG[( 0 + ml)*33 + o] = make_float2(r0, i0);
        sG[(16 + ml)*33 + o] = make_float2(r1, i1);
        sG[(32 + ml)*33 + o] = make_float2(r2, i2);
        sG[(48 + ml)*33 + o] = make_float2(r3, i3);
    }
    __syncthreads();

    // stage 3: inverse DFT over o -> c, scaled. thread = (c, m); loop b.
    {
        int c = t & 31, ml = t >> 5;
        #pragma unroll
        for (int b = 0; b < 4; b++) {
            float re = 0.f, im = 0.f;
            #pragma unroll 4
            for (int o = 0; o < 32; o++) {
                float2 g = sG[(b*16 + ml)*33 + o];
                float2 w = tw[(o*c) & 31];       // e^{+i}
                re += g.x*w.x - g.y*w.y;
                im += g.x*w.y + g.y*w.x;
            }
            g_A5[((size_t)(b*4096 + m0 + ml))*32 + c] =
                make_float2(re*SCALE, im*SCALE);
        }
    }
}

// ============================================================================
// Kernel C: inverse DFT over ky (16->64) and kz (16->64 real), radix-4 on the
// output side. Block = (b, Xs, cg of 8 channels).
// ============================================================================
__global__ __launch_bounds__(512) void kC(float* __restrict__ out) {
    __shared__ float2 sIn[16*16*8];   // [ky][kz][c]
    __shared__ float2 t1[64*128];     // [y][kz*8+c]
    __shared__ float2 tw[64];
    int bid = blockIdx.x;             // b*64 + Xs*4 + cg
    int cg = bid & 3;
    int Xs = (bid >> 2) & 15;
    int b  = bid >> 6;
    int t = threadIdx.x;
    if (t < 64) {
        double ang = 2.0*PI_D*(double)t/64.0;
        tw[t] = make_float2((float)cos(ang), (float)sin(ang));
    }
    #pragma unroll
    for (int r = 0; r < 4; r++) {
        int idx = t + r*512;
        int c = idx & 7, kz = (idx >> 3) & 15, ky = idx >> 7;
        sIn[idx] = g_A5[((size_t)(b*4096 + Xs*256 + ky*16 + kz))*32 + cg*8 + c];
    }
    __syncthreads();

    // ---- stage 1: inverse ky-DFT (16 -> 64), output radix-4.
    // thread = (c, kz, yq); handles y0 = yq*4 + j, outputs y0 + 16p.
    {
        int c = t & 7, kz = (t >> 3) & 15, yq = t >> 7;
        float akr[16], aki[16];
        #pragma unroll
        for (int k = 0; k < 16; k++) {
            float2 a = sIn[(k*16 + kz)*8 + c];
            akr[k] = a.x; aki[k] = a.y;
        }
        #pragma unroll
        for (int j = 0; j < 4; j++) {
            int y0 = yq*4 + j;
            float Tr[4], Ti[4];
            #pragma unroll
            for (int r = 0; r < 4; r++) {
                float trr = 0.f, tii = 0.f;
                #pragma unroll
                for (int m = 0; m < 4; m++) {
                    int k = 4*m + r;
                    float2 w = tw[(k*y0)&63];    // e^{+i}
                    trr += akr[k]*w.x - aki[k]*w.y;
                    tii += akr[k]*w.y + aki[k]*w.x;
                }
                Tr[r] = trr; Ti[r] = tii;
            }
            float Er=Tr[0]+Tr[2], Ei=Ti[0]+Ti[2];
            float Fr=Tr[0]-Tr[2], Fi=Ti[0]-Ti[2];
            float Gr=Tr[1]+Tr[3], Gi=Ti[1]+Ti[3];
            float Hr=Tr[1]-Tr[3], Hi=Ti[1]-Ti[3];
            t1[(y0   )*128 + kz*8 + c] = make_float2(Er+Gr, Ei+Gi);  // p=0
            t1[(y0+16)*128 + kz*8 + c] = make_float2(Fr-Hi, Fi+Hr);  // p=1: F+iH
            t1[(y0+32)*128 + kz*8 + c] = make_float2(Er-Gr, Ei-Gi);  // p=2
            t1[(y0+48)*128 + kz*8 + c] = make_float2(Fr+Hi, Fi-Hr);  // p=3: F-iH
        }
    }
    __syncthreads();

    // ---- stage 2: inverse kz-DFT (16 -> 64), real part, output radix-4.
    // thread = (c, z0, yq); twiddles for this z0 register-cached.
    {
        int c = t & 7, z0 = (t >> 3) & 15, yq = t >> 7;
        float cwv[16], swv[16];
        #pragma unroll
        for (int k = 0; k < 16; k++) {
            float2 w = tw[(k*z0)&63];
            cwv[k] = w.x; swv[k] = w.y;
        }
        float* dst = out + ((((size_t)b*64 + Xs)*64)*64)*32 + (size_t)z0*32 + cg*8 + c;
        for (int yy = yq*16; yy < yq*16 + 16; yy++) {
            float t0r=0.f, t2r=0.f, t1r=0.f, t1i=0.f, t3r=0.f, t3i=0.f;
            #pragma unroll
            for (int m = 0; m < 4; m++) {
                { int k=4*m;   float2 a=t1[yy*128+k*8+c]; t0r += a.x*cwv[k]-a.y*swv[k]; }
                { int k=4*m+2; float2 a=t1[yy*128+k*8+c]; t2r += a.x*cwv[k]-a.y*swv[k]; }
                { int k=4*m+1; float2 a=t1[yy*128+k*8+c]; t1r += a.x*cwv[k]-a.y*swv[k];
                                                          t1i += a.x*swv[k]+a.y*cwv[k]; }
                { int k=4*m+3; float2 a=t1[yy*128+k*8+c]; t3r += a.x*cwv[k]-a.y*swv[k];
                                                          t3i += a.x*swv[k]+a.y*cwv[k]; }
            }
            float t02p=t0r+t2r, t02m=t0r-t2r, t13p=t1r+t3r, h=t1i-t3i;
            size_t base = (size_t)yy*2048;
            dst[base        ] = t02p + t13p;   // z = z0
            dst[base +  512 ] = t02m - h;      // z = z0+16
            dst[base + 1024 ] = t02p - t13p;   // z = z0+32
            dst[base + 1536 ] = t02m + h;      // z = z0+48
        }
    }
}

extern "C" void kernel_launch(void* const* d_in, const int* in_sizes, int n_in,
                              void* d_out, int out_size) {
    const float* x  = (const float*)d_in[0];
    const float* wr = (const float*)d_in[1];
    const float* wi = (const float*)d_in[2];
    float* out = (float*)d_out;

    // Output is exactly zero for X >= 16 (no X-axis transform; out_ft zero-padded)
    for (int b = 0; b < 4; b++) {
        size_t off = (((size_t)b*64 + 16)*64*64)*32;
        cudaMemsetAsync(out + off, 0, (size_t)48*64*64*32*sizeof(float), 0);
    }

    kA<<<256, 512>>>(x);        // forward z,y DFT (radix-4)
    kB<<<256, 512>>>(wr, wi);   // c-DFT + mix + inverse o-DFT
    kC<<<256, 512>>>(out);      // inverse ky,kz DFT (radix-4)
}